// round 12
// baseline (speedup 1.0000x reference)
#include <cuda_runtime.h>
#include <math.h>

// ---------------- static scratch (zero-initialized .bss; halos re-zeroed each launch) ----
// A: dual-use: conv1 polyphase out (32*64ch*4ph planes of 66x66 = 35,684,352)
//    then deconv1 out (32*64 planes of 130x130 = 34,611,200)
__device__ float g_bufA[35684352];
__device__ float g_bufB[17842176];  // 32*128 planes of 66*66
__device__ float g_bufC[17842176];  // 32*128 planes of 66*66
__device__ float g_bufD[ 4194304];  // 32*32*64*64 (unpadded)
__device__ float g_bufE[ 8388608];  // 32*64*64*64 z (unpadded)
__device__ float g_bufF[ 8921088];  // 32*64 planes of 66*66 (quantized)
__device__ float g_loss_sum;
__device__ float g_cnorm[512];

// ---------------- packed f32x2 helpers ----------------
typedef unsigned long long u64;
__device__ __forceinline__ u64 ffma2(u64 a, u64 b, u64 c){
    u64 d; asm("fma.rn.f32x2 %0, %1, %2, %3;" : "=l"(d) : "l"(a), "l"(b), "l"(c)); return d;
}
__device__ __forceinline__ u64 bcast2(float v){
    u64 d; asm("mov.b64 %0, {%1, %1};" : "=l"(d) : "f"(v)); return d;
}
__device__ __forceinline__ u64 pack2(float lo, float hi){
    u64 d; asm("mov.b64 %0, {%1, %2};" : "=l"(d) : "f"(lo), "f"(hi)); return d;
}
__device__ __forceinline__ void unpack2(u64 v, float& lo, float& hi){
    asm("mov.b64 {%0, %1}, %2;" : "=f"(lo), "=f"(hi) : "l"(v));
}

// ---------------- F(2x2,2x2) transform helpers ----------------
// 1D: Bt=[[1,0,-1],[0,1,1],[0,-1,1]], G=[[1,0],[.5,.5],[.5,-.5]], At=[[1,1,1],[0,1,-1]]
__device__ __forceinline__ void bt3x3(const float d[9], float V[9]){
    float r[9];
#pragma unroll
    for(int c=0;c<3;c++){
        r[0*3+c]=d[0*3+c]-d[2*3+c];
        r[1*3+c]=d[1*3+c]+d[2*3+c];
        r[2*3+c]=d[2*3+c]-d[1*3+c];
    }
#pragma unroll
    for(int rr=0;rr<3;rr++){
        V[rr*3+0]=r[rr*3+0]-r[rr*3+2];
        V[rr*3+1]=r[rr*3+1]+r[rr*3+2];
        V[rr*3+2]=r[rr*3+2]-r[rr*3+1];
    }
}
__device__ __forceinline__ void g2u3(const float g[4], float U[9]){
    // rows: t0=g row0; t1=.5(row0+row1); t2=.5(row0-row1); then cols same pattern
    float t[6];
#pragma unroll
    for(int c=0;c<2;c++){
        t[0*2+c]=g[0*2+c];
        t[1*2+c]=0.5f*(g[0*2+c]+g[1*2+c]);
        t[2*2+c]=0.5f*(g[0*2+c]-g[1*2+c]);
    }
#pragma unroll
    for(int r=0;r<3;r++){
        U[r*3+0]=t[r*2+0];
        U[r*3+1]=0.5f*(t[r*2+0]+t[r*2+1]);
        U[r*3+2]=0.5f*(t[r*2+0]-t[r*2+1]);
    }
}

// ---------------- halo zeroing ----------------
template<int NP,int H,int W>
__global__ void zero_halo(float* __restrict__ buf){
    constexpr int PW=W+2, PH=H+2;
    constexpr int RING=2*PW+2*H;
    int i=blockIdx.x*blockDim.x+threadIdx.x;
    if (i>=NP*RING) return;
    int p=i/RING, r=i%RING, off;
    if (r<PW) off=r;
    else if (r<2*PW) off=(PH-1)*PW+(r-PW);
    else { int s=r-2*PW; int row=s>>1; off=(row+1)*PW+((s&1)?PW-1:0); }
    buf[(size_t)p*PW*PH+off]=0.f;
}

// ---------------- direct conv (conv1 + 1x1 layers), packed-FFMA2 ----------------
// POLY: store output in polyphase layout (4 planes of 66x66 per cout).
template<int Cin,int Cout,int Hin,int Win,int K,int S,int P,int CG,int PX,int CB,
         int IPW,int OPW,bool CHECKED,bool RIN,bool ROUT,bool HASADD,bool POLY>
__global__ __launch_bounds__(256) void convp(
    const float* __restrict__ in, const float* __restrict__ w,
    const float* __restrict__ bias, const float* __restrict__ addp,
    float* __restrict__ out)
{
    constexpr int Hout=(Hin+2*P-K)/S+1, Wout=(Win+2*P-K)/S+1;
    constexpr int HW=Hout*Wout;
    constexpr int TAPS=K*K;
    constexpr int IPADH=(IPW>Win)?Hin+2:Hin;
    constexpr int IPLANE=IPW*IPADH;
    constexpr int IOFF=(IPW>Win)?(IPW+1):0;
    constexpr int OPADH=(OPW>Wout)?Hout+2:Hout;
    constexpr int OPLANE=OPW*OPADH;
    constexpr int OOFF=(OPW>Wout)?(OPW+1):0;
    constexpr int RJ=256/Wout;
    static_assert(HW%(256*PX)==0 && 256%Wout==0, "grid exactness");
    static_assert(CG%4==0, "packed path needs CG%4==0");
    constexpr int CGH=CG/2;
    constexpr int WSZ=CB*TAPS*CG;
    __shared__ __align__(16) float sw[WSZ];

    const int co0=blockIdx.y*CG, n=blockIdx.z;
    const int base=blockIdx.x*(256*PX)+threadIdx.x;
    const int oh0=base/Wout, ow=base%Wout;

    u64 acc[PX][CGH];
#pragma unroll
    for(int q=0;q<CGH;q++){ u64 b=pack2(bias[co0+2*q], bias[co0+2*q+1]);
#pragma unroll
        for(int j=0;j<PX;j++) acc[j][q]=b; }

    const float* inb = in + (size_t)n*Cin*IPLANE + IOFF;

    for (int cb0=0; cb0<Cin; cb0+=CB){
        __syncthreads();
        for(int i=threadIdx.x;i<WSZ;i+=256){
            int g=i%CG, rest=i/CG;
            sw[i]=w[(size_t)(co0+g)*(Cin*TAPS)+cb0*TAPS+rest];
        }
        __syncthreads();
#pragma unroll 2
        for(int cl=0; cl<CB; cl++){
            const float* ip = inb + (size_t)(cb0+cl)*IPLANE;
#pragma unroll
            for(int t=0;t<TAPS;t++){
                const int kh=t/K, kw=t%K;
                u64 wv[CGH];
                const ulonglong2* w4=(const ulonglong2*)(sw+(cl*TAPS+t)*CG);
#pragma unroll
                for(int q=0;q<CG/4;q++){ ulonglong2 f=w4[q]; wv[2*q]=f.x; wv[2*q+1]=f.y; }
#pragma unroll
                for(int j=0;j<PX;j++){
                    const int oh=oh0+j*RJ;
                    const int ih=oh*S-P+kh, iw=ow*S-P+kw;
                    float v;
                    if constexpr (CHECKED){
                        v=(ih>=0&&ih<Hin&&iw>=0&&iw<Win)? __ldg(ip+ih*IPW+iw):0.f;
                    } else {
                        v=__ldg(ip+ih*IPW+iw);
                    }
                    if constexpr (RIN) v=fmaxf(v,0.f);
                    u64 vb=bcast2(v);
#pragma unroll
                    for(int q=0;q<CGH;q++) acc[j][q]=ffma2(vb,wv[q],acc[j][q]);
                }
            }
        }
    }

    if constexpr (POLY){
#pragma unroll
        for(int j=0;j<PX;j++){
            const int oh=oh0+j*RJ;
            const int ph2=(oh&1)*2+(ow&1);
            const size_t pos=((size_t)((oh>>1)+1))*66 + (ow>>1)+1;
#pragma unroll
            for(int q=0;q<CGH;q++){
                float r0,r1; unpack2(acc[j][q],r0,r1);
                if constexpr (ROUT){ r0=fmaxf(r0,0.f); r1=fmaxf(r1,0.f); }
                out[((size_t)(n*Cout+co0+2*q  )*4+ph2)*4356 + pos]=r0;
                out[((size_t)(n*Cout+co0+2*q+1)*4+ph2)*4356 + pos]=r1;
            }
        }
    } else {
        float* ob = out + (size_t)n*Cout*OPLANE + OOFF;
        const float* ab = HASADD ? (addp + (size_t)n*Cout*OPLANE + OOFF) : nullptr;
#pragma unroll
        for(int j=0;j<PX;j++){
            const int oh=oh0+j*RJ;
#pragma unroll
            for(int q=0;q<CGH;q++){
                float r0,r1; unpack2(acc[j][q],r0,r1);
                size_t i0=(size_t)(co0+2*q  )*OPLANE + oh*OPW + ow;
                size_t i1=(size_t)(co0+2*q+1)*OPLANE + oh*OPW + ow;
                if constexpr (HASADD){ r0+=ab[i0]; r1+=ab[i1]; }
                if constexpr (ROUT){ r0=fmaxf(r0,0.f); r1=fmaxf(r1,0.f); }
                ob[i0]=r0; ob[i1]=r1;
            }
        }
    }
}

// ---------------- Winograd F(2x2,3x3), CG=16 x 64 tiles (unchanged from R8) ----------------
template<int Cin,int Cout,int OPW,bool RIN>
__global__ __launch_bounds__(256) void winog(
    const float* __restrict__ in, const float* __restrict__ w,
    const float* __restrict__ bias, float* __restrict__ out)
{
    constexpr int CB=4, CG=16, TJ=4;
    constexpr int IPLANE=66*66;
    constexpr int OPADH=(OPW>64)?66:64;
    constexpr int OPLANE=OPW*OPADH;
    constexpr int OOFF=(OPW>64)?(OPW+1):0;
    __shared__ __align__(16) float sU[16*CB*CG];
    __shared__ __align__(16) float sV[8704];

    const int tid=threadIdx.x;
    const int p=tid>>4, tg=tid&15;
    const int co0=blockIdx.y*CG, n=blockIdx.z, bx=blockIdx.x;
    const float* inb = in + (size_t)n*Cin*IPLANE;

    u64 macc2[TJ][CG/2];
#pragma unroll
    for(int j=0;j<TJ;j++)
#pragma unroll
        for(int q=0;q<CG/2;q++) macc2[j][q]=0ull;

    for(int cb0=0; cb0<Cin; cb0+=CB){
        __syncthreads();
        if (tid < CB*CG){
            int cl=tid>>4, g=tid&15;
            const float* wp = w + ((size_t)(co0+g)*Cin + (cb0+cl))*9;
            float a0=wp[0],a1=wp[1],a2=wp[2],a3=wp[3],a4=wp[4],a5=wp[5],a6=wp[6],a7=wp[7],a8=wp[8];
            float p0c0=a0,                  p0c1=a1,                  p0c2=a2;
            float p1c0=0.5f*(a0+a3+a6),    p1c1=0.5f*(a1+a4+a7),     p1c2=0.5f*(a2+a5+a8);
            float p2c0=0.5f*(a0-a3+a6),    p2c1=0.5f*(a1-a4+a7),     p2c2=0.5f*(a2-a5+a8);
            float p3c0=a6,                  p3c1=a7,                  p3c2=a8;
            float U[16];
            U[ 0]=p0c0; U[ 1]=0.5f*(p0c0+p0c1+p0c2); U[ 2]=0.5f*(p0c0-p0c1+p0c2); U[ 3]=p0c2;
            U[ 4]=p1c0; U[ 5]=0.5f*(p1c0+p1c1+p1c2); U[ 6]=0.5f*(p1c0-p1c1+p1c2); U[ 7]=p1c2;
            U[ 8]=p2c0; U[ 9]=0.5f*(p2c0+p2c1+p2c2); U[10]=0.5f*(p2c0-p2c1+p2c2); U[11]=p2c2;
            U[12]=p3c0; U[13]=0.5f*(p3c0+p3c1+p3c2); U[14]=0.5f*(p3c0-p3c1+p3c2); U[15]=p3c2;
#pragma unroll
            for(int q=0;q<16;q++) sU[q*(CB*CG)+cl*CG+g]=U[q];
        }
        {
            int cl=tid>>6, tile=tid&63;
            int tr=(bx<<1)+(tile>>5), tc=tile&31;
            const float* ip = inb + (size_t)(cb0+cl)*IPLANE + (size_t)(tr*2)*66 + tc*2;
            float d[16];
#pragma unroll
            for(int r=0;r<4;r++)
#pragma unroll
                for(int c=0;c<4;c++){
                    float v=__ldg(ip + r*66 + c);
                    if constexpr (RIN) v=fmaxf(v,0.f);
                    d[r*4+c]=v;
                }
            float w0[4],w1[4],w2[4],w3[4];
#pragma unroll
            for(int c=0;c<4;c++){
                w0[c]=d[c]-d[8+c];
                w1[c]=d[4+c]+d[8+c];
                w2[c]=d[8+c]-d[4+c];
                w3[c]=d[4+c]-d[12+c];
            }
            float V[16];
            V[ 0]=w0[0]-w0[2]; V[ 1]=w0[1]+w0[2]; V[ 2]=w0[2]-w0[1]; V[ 3]=w0[1]-w0[3];
            V[ 4]=w1[0]-w1[2]; V[ 5]=w1[1]+w1[2]; V[ 6]=w1[2]-w1[1]; V[ 7]=w1[1]-w1[3];
            V[ 8]=w2[0]-w2[2]; V[ 9]=w2[1]+w2[2]; V[10]=w2[2]-w2[1]; V[11]=w2[1]-w2[3];
            V[12]=w3[0]-w3[2]; V[13]=w3[1]+w3[2]; V[14]=w3[2]-w3[1]; V[15]=w3[1]-w3[3];
#pragma unroll
            for(int q=0;q<16;q++) sV[q*256 + tid] = V[q];
        }
        __syncthreads();
#pragma unroll
        for(int cl=0;cl<CB;cl++){
            const ulonglong2* u2=(const ulonglong2*)(sU + p*(CB*CG) + cl*CG);
            u64 uv2[CG/2];
#pragma unroll
            for(int q=0;q<CG/4;q++){ ulonglong2 f=u2[q]; uv2[2*q]=f.x; uv2[2*q+1]=f.y; }
            float4 va=*(const float4*)(sV + p*256 + cl*64 + tg*4);
            u64 vv2[TJ]={bcast2(va.x),bcast2(va.y),bcast2(va.z),bcast2(va.w)};
#pragma unroll
            for(int j=0;j<TJ;j++)
#pragma unroll
                for(int q=0;q<CG/2;q++)
                    macc2[j][q]=ffma2(vv2[j],uv2[q],macc2[j][q]);
        }
    }

    float macc[TJ][CG];
#pragma unroll
    for(int j=0;j<TJ;j++)
#pragma unroll
        for(int q=0;q<CG/2;q++) unpack2(macc2[j][q], macc[j][2*q], macc[j][2*q+1]);

    float* ob = out + (size_t)n*Cout*OPLANE + OOFF;
#pragma unroll
    for(int gh=0; gh<2; gh++){
        __syncthreads();
#pragma unroll
        for(int gs=0;gs<8;gs++)
#pragma unroll
            for(int j=0;j<TJ;j++){
                int unit = gs*64 + tg*TJ + j;
                sV[unit*17 + p] = macc[j][gh*8+gs];
            }
        __syncthreads();
#pragma unroll
        for(int k=0;k<2;k++){
            int unit = tid*2+k;
            int gs = unit>>6, tile = unit&63;
            int tr=(bx<<1)+(tile>>5), tc=tile&31;
            float m[16];
#pragma unroll
            for(int q=0;q<16;q++) m[q]=sV[unit*17+q];
            float s0[4], s1[4];
#pragma unroll
            for(int c=0;c<4;c++){ s0[c]=m[c]+m[4+c]+m[8+c]; s1[c]=m[4+c]-m[8+c]-m[12+c]; }
            int co=co0+gh*8+gs;
            float b=bias[co];
            float y00=s0[0]+s0[1]+s0[2]+b;
            float y01=s0[1]-s0[2]-s0[3]+b;
            float y10=s1[0]+s1[1]+s1[2]+b;
            float y11=s1[1]-s1[2]-s1[3]+b;
            float* op = ob + (size_t)co*OPLANE + (size_t)(tr*2)*OPW + tc*2;
            op[0]=y00; op[1]=y01;
            op[OPW]=y10; op[OPW+1]=y11;
        }
    }
}

// ---------------- Winograd F(2x2,2x2) for conv2: 4 polyphase k2s1 convs summed -------------
// 288 threads = 9 warps. Warp = transform point p (0..8); lanes = 32 tile-groups x TJ=2 tiles.
// Input: polyphase planes [(cin*4+phase)] of 66x66 (halo-padded). Output: B66, bias+ReLU.
__global__ __launch_bounds__(288) void winog2_c2(
    const float* __restrict__ in, const float* __restrict__ w,
    const float* __restrict__ bias, float* __restrict__ out)
{
    constexpr int Cin=64, Cout=128, CB=4, CG=16;
    __shared__ __align__(16) float sh[7232];   // sU[576] | sV[2304] / sM[512*13]
    float* sU=sh; float* sV=sh+576; float* sM=sh+576;

    const int t=threadIdx.x;
    const int p=t>>5, tg=t&31;
    const int co0=blockIdx.y*CG, n=blockIdx.z, bx=blockIdx.x;
    const int trow0=bx*2;

    u64 acc[2][CG/2];
#pragma unroll
    for(int j=0;j<2;j++)
#pragma unroll
        for(int q=0;q<CG/2;q++) acc[j][q]=0ull;

    for(int ph=0; ph<4; ph++){
        const int rb=ph>>1, cb=ph&1;
        const int dr=rb?-1:0, dc=cb?-1:0;
        for(int cb0=0; cb0<Cin; cb0+=CB){
            __syncthreads();
            // U = G g Gt; g[a][c] = w[co][ci][2a+(1-rb)][2c+(1-cb)]
            if (t < CB*CG){
                int cl=t>>4, g=t&15;
                const float* wp = w + ((size_t)(co0+g)*Cin + (cb0+cl))*16;
                float g2[4];
#pragma unroll
                for(int a=0;a<2;a++)
#pragma unroll
                    for(int c=0;c<2;c++)
                        g2[a*2+c]=wp[(2*a+(1-rb))*4 + (2*c+(1-cb))];
                float U[9]; g2u3(g2,U);
#pragma unroll
                for(int q=0;q<9;q++) sU[q*64 + cl*16 + g]=U[q];
            }
            // V = Bt d B; 256 units (cl,tile)
            if (t < 256){
                int cl=t>>6, tile=t&63;
                int tr=trow0+(tile>>5), tc=tile&31;
                const float* pb = in + ((size_t)(n*Cin+cb0+cl)*4+ph)*4356;
                float d[9];
#pragma unroll
                for(int r=0;r<3;r++)
#pragma unroll
                    for(int c=0;c<3;c++)
                        d[r*3+c]=__ldg(pb + (size_t)(2*tr+dr+r+1)*66 + (2*tc+dc+c+1));
                float V[9]; bt3x3(d,V);
#pragma unroll
                for(int q=0;q<9;q++) sV[q*256 + t]=V[q];
            }
            __syncthreads();
#pragma unroll
            for(int cl=0;cl<CB;cl++){
                const ulonglong2* u2=(const ulonglong2*)(sU + p*64 + cl*16);
                u64 uv[CG/2];
#pragma unroll
                for(int q=0;q<CG/4;q++){ ulonglong2 f=u2[q]; uv[2*q]=f.x; uv[2*q+1]=f.y; }
                float2 vv=*(const float2*)(sV + p*256 + cl*64 + tg*2);
                u64 v0=bcast2(vv.x), v1=bcast2(vv.y);
#pragma unroll
                for(int q=0;q<CG/2;q++){
                    acc[0][q]=ffma2(v0,uv[q],acc[0][q]);
                    acc[1][q]=ffma2(v1,uv[q],acc[1][q]);
                }
            }
        }
    }

    // epilogue: Y = At M A + bias, ReLU -> B66. Two cout halves.
    float* ob = out + (size_t)n*Cout*4356;
#pragma unroll
    for(int gh=0; gh<2; gh++){
        __syncthreads();
#pragma unroll
        for(int j=0;j<2;j++){
            int tile=tg*2+j;
#pragma unroll
            for(int q=gh*4;q<gh*4+4;q++){
                float r0,r1; unpack2(acc[j][q],r0,r1);
                int g0=2*(q-gh*4);
                sM[(tile*8+g0  )*13+p]=r0;
                sM[(tile*8+g0+1)*13+p]=r1;
            }
        }
        __syncthreads();
#pragma unroll
        for(int k=0;k<2;k++){
            int unit=k*288+t;
            if (unit<512){
                int tile=unit>>3, gl=unit&7;
                int tr=trow0+(tile>>5), tc=tile&31;
                float m[9];
#pragma unroll
                for(int q=0;q<9;q++) m[q]=sM[unit*13+q];
                float T0[3],T1[3];
#pragma unroll
                for(int c=0;c<3;c++){ T0[c]=m[c]+m[3+c]+m[6+c]; T1[c]=m[3+c]-m[6+c]; }
                int co=co0+gh*8+gl;
                float b=bias[co];
                float y00=fmaxf(T0[0]+T0[1]+T0[2]+b,0.f);
                float y01=fmaxf(T0[1]-T0[2]+b,0.f);
                float y10=fmaxf(T1[0]+T1[1]+T1[2]+b,0.f);
                float y11=fmaxf(T1[1]-T1[2]+b,0.f);
                float* op = ob + (size_t)co*4356 + (size_t)(2*tr+1)*66 + 2*tc+1;
                op[0]=y00; op[1]=y01; op[66]=y10; op[67]=y11;
            }
        }
    }
}

// ---------------- Winograd F(2x2,2x2) for deconv1: 4 parity classes, k2s1 each -------------
// Class from grid.x; kernel flipped: g[a][c] = w[ci][co][3-ph-2a][3-pw-2c].
// Input B66; output A130 (interior), bias+ReLU.
__global__ __launch_bounds__(288) void winog2_d1(
    const float* __restrict__ in, const float* __restrict__ w,
    const float* __restrict__ bias, float* __restrict__ out)
{
    constexpr int Cin=128, Cout=64, CB=4, CG=16;
    __shared__ __align__(16) float sh[7232];
    float* sU=sh; float* sV=sh+576; float* sM=sh+576;

    const int t=threadIdx.x;
    const int p=t>>5, tg=t&31;
    const int cls=blockIdx.x>>4, bx=blockIdx.x&15;
    const int ph=cls>>1, pw=cls&1;
    const int co0=blockIdx.y*CG, n=blockIdx.z;
    const int trow0=bx*2;

    u64 acc[2][CG/2];
#pragma unroll
    for(int j=0;j<2;j++)
#pragma unroll
        for(int q=0;q<CG/2;q++) acc[j][q]=0ull;

    for(int cb0=0; cb0<Cin; cb0+=CB){
        __syncthreads();
        if (t < CB*CG){
            int cl=t>>4, g=t&15;
            const float* wp = w + ((size_t)(cb0+cl)*Cout + (co0+g))*16;
            float g2[4];
#pragma unroll
            for(int a=0;a<2;a++)
#pragma unroll
                for(int c=0;c<2;c++)
                    g2[a*2+c]=wp[(3-ph-2*a)*4 + (3-pw-2*c)];
            float U[9]; g2u3(g2,U);
#pragma unroll
            for(int q=0;q<9;q++) sU[q*64 + cl*16 + g]=U[q];
        }
        if (t < 256){
            int cl=t>>6, tile=t&63;
            int tr=trow0+(tile>>5), tc=tile&31;
            const float* pb = in + (size_t)(n*Cin+cb0+cl)*4356;
            float d[9];
#pragma unroll
            for(int r=0;r<3;r++)
#pragma unroll
                for(int c=0;c<3;c++)
                    d[r*3+c]=__ldg(pb + (size_t)(2*tr+ph+r)*66 + (2*tc+pw+c));
            float V[9]; bt3x3(d,V);
#pragma unroll
            for(int q=0;q<9;q++) sV[q*256 + t]=V[q];
        }
        __syncthreads();
#pragma unroll
        for(int cl=0;cl<CB;cl++){
            const ulonglong2* u2=(const ulonglong2*)(sU + p*64 + cl*16);
            u64 uv[CG/2];
#pragma unroll
            for(int q=0;q<CG/4;q++){ ulonglong2 f=u2[q]; uv[2*q]=f.x; uv[2*q+1]=f.y; }
            float2 vv=*(const float2*)(sV + p*256 + cl*64 + tg*2);
            u64 v0=bcast2(vv.x), v1=bcast2(vv.y);
#pragma unroll
            for(int q=0;q<CG/2;q++){
                acc[0][q]=ffma2(v0,uv[q],acc[0][q]);
                acc[1][q]=ffma2(v1,uv[q],acc[1][q]);
            }
        }
    }

    float* ob = out + (size_t)n*Cout*16900;
#pragma unroll
    for(int gh=0; gh<2; gh++){
        __syncthreads();
#pragma unroll
        for(int j=0;j<2;j++){
            int tile=tg*2+j;
#pragma unroll
            for(int q=gh*4;q<gh*4+4;q++){
                float r0,r1; unpack2(acc[j][q],r0,r1);
                int g0=2*(q-gh*4);
                sM[(tile*8+g0  )*13+p]=r0;
                sM[(tile*8+g0+1)*13+p]=r1;
            }
        }
        __syncthreads();
#pragma unroll
        for(int k=0;k<2;k++){
            int unit=k*288+t;
            if (unit<512){
                int tile=unit>>3, gl=unit&7;
                int tr=trow0+(tile>>5), tc=tile&31;
                float m[9];
#pragma unroll
                for(int q=0;q<9;q++) m[q]=sM[unit*13+q];
                float T0[3],T1[3];
#pragma unroll
                for(int c=0;c<3;c++){ T0[c]=m[c]+m[3+c]+m[6+c]; T1[c]=m[3+c]-m[6+c]; }
                int co=co0+gh*8+gl;
                float b=bias[co];
                float y[2][2];
                y[0][0]=fmaxf(T0[0]+T0[1]+T0[2]+b,0.f);
                y[0][1]=fmaxf(T0[1]-T0[2]+b,0.f);
                y[1][0]=fmaxf(T1[0]+T1[1]+T1[2]+b,0.f);
                y[1][1]=fmaxf(T1[1]-T1[2]+b,0.f);
                float* op = ob + (size_t)co*16900;
#pragma unroll
                for(int i=0;i<2;i++){
                    int oh=2*(2*tr+i)+ph;
#pragma unroll
                    for(int jj=0;jj<2;jj++){
                        int ow=2*(2*tc+jj)+pw;
                        op[(size_t)(oh+1)*130 + ow+1]=y[i][jj];
                    }
                }
            }
        }
    }
}

// ---------------- ConvTranspose2d k=4 s=2 p=1 gather (deconv2 only now) ----------------
template<int Cin,int Cout,int Hin,int Win,int CG,int PX,int IPW,int OPW,bool ROUT,bool TANH>
__global__ __launch_bounds__(256) void deconvp(
    const float* __restrict__ in, const float* __restrict__ w,
    const float* __restrict__ bias, float* __restrict__ out)
{
    constexpr int Hout=Hin*2, Wout=Win*2;
    constexpr int QHW=Hin*Win;
    constexpr int TILES=QHW/(256*PX);
    static_assert(QHW%(256*PX)==0 && 256%Win==0, "grid exactness");
    constexpr int IPLANE=IPW*(Hin+2);
    constexpr int IOFF=IPW+1;
    constexpr int OPADH=(OPW>Wout)?Hout+2:Hout;
    constexpr int OPLANE=OPW*OPADH;
    constexpr int OOFF=(OPW>Wout)?(OPW+1):0;
    constexpr int RJ=256/Win;
    constexpr bool PKD=(CG%4==0);
    constexpr int CGH=PKD?CG/2:1;
    constexpr int WSZ=Cin*4*CG;
    __shared__ __align__(16) float sw[WSZ];

    const int cls=blockIdx.x/TILES, tile=blockIdx.x%TILES;
    const int ph=cls>>1, pw=cls&1;
    const int co0=blockIdx.y*CG, n=blockIdx.z;

    for (int i=threadIdx.x;i<WSZ;i+=256){
        int g=i%CG, rest=i/CG;
        int ci=rest>>2, t=rest&3;
        int kh=(1-ph)+2*(t>>1), kw=(1-pw)+2*(t&1);
        sw[i]=w[(((size_t)ci*Cout+co0+g)*4+kh)*4+kw];
    }
    __syncthreads();

    const int base=tile*(256*PX)+threadIdx.x;
    const int qh0=base/Win, qw=base%Win;

    u64   acc2[PX][CGH];
    float accs[PX][PKD?1:CG];
    if constexpr (PKD){
#pragma unroll
        for(int q=0;q<CGH;q++){ u64 b=pack2(bias[co0+2*q], bias[co0+2*q+1]);
#pragma unroll
            for(int j=0;j<PX;j++) acc2[j][q]=b; }
    } else {
#pragma unroll
        for(int g=0;g<CG;g++){ float b=bias[co0+g];
#pragma unroll
            for(int j=0;j<PX;j++) accs[j][g]=b; }
    }

    const float* inb = in + (size_t)n*Cin*IPLANE + IOFF;
#pragma unroll 1
    for(int ci=0;ci<Cin;ci++){
        const float* ip = inb + (size_t)ci*IPLANE;
        float v[PX][4];
#pragma unroll
        for(int j=0;j<PX;j++){
            const int qh=qh0+j*RJ;
#pragma unroll
            for(int th=0;th<2;th++){
                const int ih=qh+ph-th;
#pragma unroll
                for(int tw=0;tw<2;tw++){
                    const int iw=qw+pw-tw;
                    v[j][th*2+tw]=__ldg(ip+ih*IPW+iw);
                }
            }
        }
#pragma unroll
        for(int t=0;t<4;t++){
            if constexpr (PKD){
                u64 wv[CGH];
                const ulonglong2* w4=(const ulonglong2*)(sw+(ci*4+t)*CG);
#pragma unroll
                for(int q=0;q<CG/4;q++){ ulonglong2 f=w4[q]; wv[2*q]=f.x; wv[2*q+1]=f.y; }
#pragma unroll
                for(int j=0;j<PX;j++){
                    u64 vb=bcast2(v[j][t]);
#pragma unroll
                    for(int q=0;q<CGH;q++) acc2[j][q]=ffma2(vb,wv[q],acc2[j][q]);
                }
            } else {
                float wv[CG];
#pragma unroll
                for(int g=0;g<CG;g++) wv[g]=sw[(ci*4+t)*CG+g];
#pragma unroll
                for(int j=0;j<PX;j++)
#pragma unroll
                    for(int g=0;g<CG;g++) accs[j][g]=fmaf(v[j][t],wv[g],accs[j][g]);
            }
        }
    }

    float* ob = out + (size_t)n*Cout*OPLANE + OOFF;
#pragma unroll
    for(int j=0;j<PX;j++){
        const int qh=qh0+j*RJ;
        const int oh=2*qh+ph, ow=2*qw+pw;
        if constexpr (PKD){
#pragma unroll
            for(int q=0;q<CGH;q++){
                float r0,r1; unpack2(acc2[j][q],r0,r1);
                if constexpr (ROUT){ r0=fmaxf(r0,0.f); r1=fmaxf(r1,0.f); }
                if constexpr (TANH){ r0=tanhf(r0); r1=tanhf(r1); }
                ob[(size_t)(co0+2*q  )*OPLANE + oh*OPW + ow]=r0;
                ob[(size_t)(co0+2*q+1)*OPLANE + oh*OPW + ow]=r1;
            }
        } else {
#pragma unroll
            for(int g=0;g<CG;g++){
                float r=accs[j][g];
                if constexpr (ROUT) r=fmaxf(r,0.f);
                if constexpr (TANH) r=tanhf(r);
                ob[(size_t)(co0+g)*OPLANE + oh*OPW + ow]=r;
            }
        }
    }
}

// ---------------- VQ (UNCHANGED — bit-exact reference rounding chain) ----------------
__global__ void zero_loss_k(){ g_loss_sum = 0.f; }

__global__ void cnorm_k(const float* __restrict__ cb){
    int c = blockIdx.x*blockDim.x + threadIdx.x;
    if (c < 512){
        float s = 0.f;
        const float* p = cb + (size_t)c*64;
#pragma unroll
        for (int d=0; d<64; d++) s = __fadd_rn(s, __fmul_rn(p[d], p[d]));
        g_cnorm[c] = s;
    }
}

__global__ __launch_bounds__(256) void vq_k(
    const float* __restrict__ z, const float* __restrict__ cb,
    float* __restrict__ quant)
{
    constexpr int D=64, NC=512, CHUNK=128;
    __shared__ __align__(16) float scode[CHUNK*D];
    __shared__ float snorm[CHUNK];
    __shared__ float sred[8];
    const int tid = threadIdx.x;
    const int p   = blockIdx.x*256 + tid;
    const int n   = p >> 12;
    const int hw  = p & 4095;
    const int h   = hw >> 6, wq = hw & 63;
    const float* zp = z + (size_t)n*D*4096 + hw;
    float zr[D];
#pragma unroll
    for (int d=0; d<D; d++) zr[d] = __ldg(zp + (size_t)d*4096);
    float zz = 0.f;
#pragma unroll
    for (int d=0; d<D; d++) zz = __fadd_rn(zz, __fmul_rn(zr[d], zr[d]));

    float best = 3.4e38f; int bidx = 0;
    for (int c0 = 0; c0 < NC; c0 += CHUNK){
        __syncthreads();
        for (int i = tid; i < CHUNK*D; i += 256) scode[i] = cb[(size_t)c0*D + i];
        if (tid < CHUNK) snorm[tid] = g_cnorm[c0 + tid];
        __syncthreads();
#pragma unroll 2
        for (int c = 0; c < CHUNK; c++){
            const float4* cp = (const float4*)(scode + c*D);
            float ip = 0.f;
#pragma unroll
            for (int q=0;q<16;q++){
                float4 e = cp[q];
                ip = fmaf(zr[4*q+0], e.x, ip);
                ip = fmaf(zr[4*q+1], e.y, ip);
                ip = fmaf(zr[4*q+2], e.z, ip);
                ip = fmaf(zr[4*q+3], e.w, ip);
            }
            float score = __fadd_rn(__fsub_rn(zz, __fmul_rn(2.f, ip)), snorm[c]);
            if (score < best){ best = score; bidx = c0 + c; }
        }
    }
    const float* cbp = cb + (size_t)bidx*D;
    float* qp = quant + (size_t)n*D*4356 + (h+1)*66 + (wq+1);
    float ssd = 0.f;
#pragma unroll
    for (int d=0; d<D; d++){
        float e  = __ldg(cbp + d);
        float df = e - zr[d];
        ssd = fmaf(df, df, ssd);
        qp[(size_t)d*4356] = e;
    }
#pragma unroll
    for (int o=16;o>0;o>>=1) ssd += __shfl_xor_sync(0xffffffffu, ssd, o);
    if ((tid & 31) == 0) sred[tid>>5] = ssd;
    __syncthreads();
    if (tid == 0){
        float s = 0.f;
#pragma unroll
        for (int i=0;i<8;i++) s += sred[i];
        atomicAdd(&g_loss_sum, s);
    }
}

__global__ void finalize_loss_k(float* __restrict__ out, int idx){
    out[idx] = 1.25f * g_loss_sum / 8388608.f;
}

// ---------------- host ----------------
extern "C" void kernel_launch(void* const* d_in, const int* in_sizes, int n_in,
                              void* d_out, int out_size)
{
    const float* x       = (const float*)d_in[0];
    const float* enc_w1  = (const float*)d_in[1];
    const float* enc_b1  = (const float*)d_in[2];
    const float* enc_w2  = (const float*)d_in[3];
    const float* enc_b2  = (const float*)d_in[4];
    const float* enc_w3  = (const float*)d_in[5];
    const float* enc_b3  = (const float*)d_in[6];
    const float* enc_rw1 = (const float*)d_in[7];
    const float* enc_rb1 = (const float*)d_in[8];
    const float* enc_rw2 = (const float*)d_in[9];
    const float* enc_rb2 = (const float*)d_in[10];
    const float* pvq_w   = (const float*)d_in[11];
    const float* pvq_b   = (const float*)d_in[12];
    const float* codebook= (const float*)d_in[13];
    const float* dec_w1  = (const float*)d_in[14];
    const float* dec_b1  = (const float*)d_in[15];
    const float* dec_rw1 = (const float*)d_in[16];
    const float* dec_rb1 = (const float*)d_in[17];
    const float* dec_rw2 = (const float*)d_in[18];
    const float* dec_rb2 = (const float*)d_in[19];
    const float* dt1_w   = (const float*)d_in[20];
    const float* dt1_b   = (const float*)d_in[21];
    const float* dt2_w   = (const float*)d_in[22];
    const float* dt2_b   = (const float*)d_in[23];
    float* out = (float*)d_out;

    float *A,*B,*C,*D,*E,*F;
    cudaGetSymbolAddress((void**)&A, g_bufA);
    cudaGetSymbolAddress((void**)&B, g_bufB);
    cudaGetSymbolAddress((void**)&C, g_bufC);
    cudaGetSymbolAddress((void**)&D, g_bufD);
    cudaGetSymbolAddress((void**)&E, g_bufE);
    cudaGetSymbolAddress((void**)&F, g_bufF);

    dim3 blk(256);

    // ---- halo re-zero ----
    zero_halo<8192,64,64><<<8320,256>>>(A);   // A polyphase halos (conv2 input)
    zero_halo<4096,64,64><<<4160,256>>>(B);
    zero_halo<4096,64,64><<<4160,256>>>(C);
    zero_halo<2048,64,64><<<2080,256>>>(F);

    // ---- Encoder ----
    // conv1: 3->64 k4 s2 p1 ReLU, x -> A(polyphase 66-pad)
    convp<3,64,256,256,4,2,1, 8,4,3, 256,130, true ,false,true ,false,true ><<<dim3(16,8,32),blk>>>(x, enc_w1, enc_b1, nullptr, A);
    // conv2: 64->128 k4 s2 p1 ReLU via polyphase Winograd F(2,2), A(poly) -> B(pad66)
    winog2_c2<<<dim3(16,8,32),288>>>(A, enc_w2, enc_b2, B);
    // A-poly consumed; re-zero A halos in 130-pad layout for deconv1 output / deconv2 input
    zero_halo<2048,128,128><<<4128,256>>>(A);
    // conv3: 128->128 k3 s1 p1 (Winograd F(2,3)), B -> C
    winog<128,128,66,false><<<dim3(16,8,32),blk>>>(B, enc_w3, enc_b3, C);
    // enc res 0
    winog<128,32,64,true><<<dim3(16,2,32),blk>>>(C, enc_rw1, enc_rb1, D);
    convp<32,128,64,64,1,1,0, 16,4,32, 64,66, false,true ,false,true ,false><<<dim3(4,8,32),blk>>>(D, enc_rw2, enc_rb2, C, B);
    // enc res 1 (+ final stack ReLU)
    winog<128,32,64,true><<<dim3(16,2,32),blk>>>(B, enc_rw1+32*128*9, enc_rb1+32, D);
    convp<32,128,64,64,1,1,0, 16,4,32, 64,66, false,true ,true ,true ,false><<<dim3(4,8,32),blk>>>(D, enc_rw2+128*32, enc_rb2+128, B, C);
    // pre-VQ 1x1: 128->64, C -> E(unpadded)
    convp<128,64,64,64,1,1,0, 16,4,128, 66,64, false,false,false,false,false><<<dim3(4,4,32),blk>>>(C, pvq_w, pvq_b, nullptr, E);

    // ---- VQ ----
    zero_loss_k<<<1,1>>>();
    cnorm_k<<<2,256>>>(codebook);
    vq_k<<<512,256>>>(E, codebook, F);

    // ---- Decoder ----
    // dec conv1: 64->128 k3 s1 p1 (Winograd F(2,3)), F(pad66) -> B
    winog<64,128,66,false><<<dim3(16,8,32),blk>>>(F, dec_w1, dec_b1, B);
    // dec res 0
    winog<128,32,64,true><<<dim3(16,2,32),blk>>>(B, dec_rw1, dec_rb1, D);
    convp<32,128,64,64,1,1,0, 16,4,32, 64,66, false,true ,false,true ,false><<<dim3(4,8,32),blk>>>(D, dec_rw2, dec_rb2, B, C);
    // dec res 1 (+ final ReLU)
    winog<128,32,64,true><<<dim3(16,2,32),blk>>>(C, dec_rw1+32*128*9, dec_rb1+32, D);
    convp<32,128,64,64,1,1,0, 16,4,32, 64,66, false,true ,true ,true ,false><<<dim3(4,8,32),blk>>>(D, dec_rw2+128*32, dec_rb2+128, C, B);
    // deconv1: 128->64 ReLU via per-class Winograd F(2,2), B(pad66) -> A(pad130)
    winog2_d1<<<dim3(64,4,32),288>>>(B, dt1_w, dt1_b, A);
    // deconv2: 64->3, tanh, A(pad130) -> out (scalar CG=3 path)
    deconvp<64,3,128,128, 3,8, 130,256, false,true ><<<dim3(32,1,32),blk>>>(A, dt2_w, dt2_b, out);

    // ---- loss scalar ----
    if (out_size > 32*3*256*256)
        finalize_loss_k<<<1,1>>>(out, out_size - 1);
}

// round 13
// speedup vs baseline: 1.0681x; 1.0681x over previous
#include <cuda_runtime.h>
#include <math.h>

// ---------------- static scratch (zero-initialized .bss; halos re-zeroed each launch) ----
__device__ float g_bufA[34611200];  // 32*64 planes of 130*130
__device__ float g_bufB[17842176];  // 32*128 planes of 66*66
__device__ float g_bufC[17842176];  // 32*128 planes of 66*66
__device__ float g_bufD[ 4194304];  // 32*32*64*64 (unpadded)
__device__ float g_bufE[ 8388608];  // 32*64*64*64 z (unpadded)
__device__ float g_bufF[ 8921088];  // 32*64 planes of 66*66 (quantized)
__device__ float g_loss_sum;
__device__ float g_cnorm[512];

// ---------------- packed f32x2 helpers (sm_103a FFMA2 path) ----------------
typedef unsigned long long u64;
__device__ __forceinline__ u64 ffma2(u64 a, u64 b, u64 c){
    u64 d; asm("fma.rn.f32x2 %0, %1, %2, %3;" : "=l"(d) : "l"(a), "l"(b), "l"(c)); return d;
}
__device__ __forceinline__ u64 bcast2(float v){
    u64 d; asm("mov.b64 %0, {%1, %1};" : "=l"(d) : "f"(v)); return d;
}
__device__ __forceinline__ u64 pack2(float lo, float hi){
    u64 d; asm("mov.b64 %0, {%1, %2};" : "=l"(d) : "f"(lo), "f"(hi)); return d;
}
__device__ __forceinline__ void unpack2(u64 v, float& lo, float& hi){
    asm("mov.b64 {%0, %1}, %2;" : "=f"(lo), "=f"(hi) : "l"(v));
}

// ---------------- halo zeroing ----------------
template<int NP,int H,int W>
__global__ void zero_halo(float* __restrict__ buf){
    constexpr int PW=W+2, PH=H+2;
    constexpr int RING=2*PW+2*H;
    int i=blockIdx.x*blockDim.x+threadIdx.x;
    if (i>=NP*RING) return;
    int p=i/RING, r=i%RING, off;
    if (r<PW) off=r;
    else if (r<2*PW) off=(PH-1)*PW+(r-PW);
    else { int s=r-2*PW; int row=s>>1; off=(row+1)*PW+((s&1)?PW-1:0); }
    buf[(size_t)p*PW*PH+off]=0.f;
}

// ---------------- direct conv (non-3x3 layers), packed-FFMA2, padded-layout aware ----------------
template<int Cin,int Cout,int Hin,int Win,int K,int S,int P,int CG,int PX,int CB,
         int IPW,int OPW,bool CHECKED,bool RIN,bool ROUT,bool HASADD>
__global__ __launch_bounds__(256) void convp(
    const float* __restrict__ in, const float* __restrict__ w,
    const float* __restrict__ bias, const float* __restrict__ addp,
    float* __restrict__ out)
{
    constexpr int Hout=(Hin+2*P-K)/S+1, Wout=(Win+2*P-K)/S+1;
    constexpr int HW=Hout*Wout;
    constexpr int TAPS=K*K;
    constexpr int IPADH=(IPW>Win)?Hin+2:Hin;
    constexpr int IPLANE=IPW*IPADH;
    constexpr int IOFF=(IPW>Win)?(IPW+1):0;
    constexpr int OPADH=(OPW>Wout)?Hout+2:Hout;
    constexpr int OPLANE=OPW*OPADH;
    constexpr int OOFF=(OPW>Wout)?(OPW+1):0;
    constexpr int RJ=256/Wout;
    static_assert(HW%(256*PX)==0 && 256%Wout==0, "grid exactness");
    static_assert(CG%4==0, "packed path needs CG%4==0");
    constexpr int CGH=CG/2;
    constexpr int WSZ=CB*TAPS*CG;
    __shared__ __align__(16) float sw[WSZ];

    const int co0=blockIdx.y*CG, n=blockIdx.z;
    const int base=blockIdx.x*(256*PX)+threadIdx.x;
    const int oh0=base/Wout, ow=base%Wout;

    u64 acc[PX][CGH];
#pragma unroll
    for(int q=0;q<CGH;q++){ u64 b=pack2(bias[co0+2*q], bias[co0+2*q+1]);
#pragma unroll
        for(int j=0;j<PX;j++) acc[j][q]=b; }

    const float* inb = in + (size_t)n*Cin*IPLANE + IOFF;

    for (int cb0=0; cb0<Cin; cb0+=CB){
        __syncthreads();
        for(int i=threadIdx.x;i<WSZ;i+=256){
            int g=i%CG, rest=i/CG;
            sw[i]=w[(size_t)(co0+g)*(Cin*TAPS)+cb0*TAPS+rest];
        }
        __syncthreads();
#pragma unroll 2
        for(int cl=0; cl<CB; cl++){
            const float* ip = inb + (size_t)(cb0+cl)*IPLANE;
#pragma unroll
            for(int t=0;t<TAPS;t++){
                const int kh=t/K, kw=t%K;
                u64 wv[CGH];
                const ulonglong2* w4=(const ulonglong2*)(sw+(cl*TAPS+t)*CG);
#pragma unroll
                for(int q=0;q<CG/4;q++){ ulonglong2 f=w4[q]; wv[2*q]=f.x; wv[2*q+1]=f.y; }
#pragma unroll
                for(int j=0;j<PX;j++){
                    const int oh=oh0+j*RJ;
                    const int ih=oh*S-P+kh, iw=ow*S-P+kw;
                    float v;
                    if constexpr (CHECKED){
                        v=(ih>=0&&ih<Hin&&iw>=0&&iw<Win)? __ldg(ip+ih*IPW+iw):0.f;
                    } else {
                        v=__ldg(ip+ih*IPW+iw);
                    }
                    if constexpr (RIN) v=fmaxf(v,0.f);
                    u64 vb=bcast2(v);
#pragma unroll
                    for(int q=0;q<CGH;q++) acc[j][q]=ffma2(vb,wv[q],acc[j][q]);
                }
            }
        }
    }

    float* ob = out + (size_t)n*Cout*OPLANE + OOFF;
    const float* ab = HASADD ? (addp + (size_t)n*Cout*OPLANE + OOFF) : nullptr;
#pragma unroll
    for(int j=0;j<PX;j++){
        const int oh=oh0+j*RJ;
#pragma unroll
        for(int q=0;q<CGH;q++){
            float r0,r1; unpack2(acc[j][q],r0,r1);
            size_t i0=(size_t)(co0+2*q  )*OPLANE + oh*OPW + ow;
            size_t i1=(size_t)(co0+2*q+1)*OPLANE + oh*OPW + ow;
            if constexpr (HASADD){ r0+=ab[i0]; r1+=ab[i1]; }
            if constexpr (ROUT){ r0=fmaxf(r0,0.f); r1=fmaxf(r1,0.f); }
            ob[i0]=r0; ob[i1]=r1;
        }
    }
}

// ---------------- Winograd F(2x2,3x3), CG=16 couts x 64 tiles, packed-FFMA2 MMA ----------------
// R13 change vs R11: input-transform loads use float2 (8x LDG.64 instead of 16x LDG.32);
// all addresses provably 8B-aligned (every index term even). Arithmetic identical.
template<int Cin,int Cout,int OPW,bool RIN>
__global__ __launch_bounds__(256) void winog(
    const float* __restrict__ in, const float* __restrict__ w,
    const float* __restrict__ bias, float* __restrict__ out)
{
    constexpr int CB=4, CG=16, TJ=4;
    constexpr int IPLANE=66*66;
    constexpr int OPADH=(OPW>64)?66:64;
    constexpr int OPLANE=OPW*OPADH;
    constexpr int OOFF=(OPW>64)?(OPW+1):0;
    __shared__ __align__(16) float sU[16*CB*CG];   // 1024 floats: [p][cl][g]
    __shared__ __align__(16) float sV[8704];       // V: [p][cl*64+tile] (4096) / M: [unit*17+p]

    const int tid=threadIdx.x;
    const int p=tid>>4, tg=tid&15;
    const int co0=blockIdx.y*CG, n=blockIdx.z, bx=blockIdx.x;
    const float* inb = in + (size_t)n*Cin*IPLANE;

    u64 macc2[TJ][CG/2];
#pragma unroll
    for(int j=0;j<TJ;j++)
#pragma unroll
        for(int q=0;q<CG/2;q++) macc2[j][q]=0ull;   // +0.0f in both lanes

    for(int cb0=0; cb0<Cin; cb0+=CB){
        __syncthreads();
        // ---- weight transform U = G g Gt (64 threads, one (cl,g) each) ----
        if (tid < CB*CG){
            int cl=tid>>4, g=tid&15;
            const float* wp = w + ((size_t)(co0+g)*Cin + (cb0+cl))*9;
            float a0=wp[0],a1=wp[1],a2=wp[2],a3=wp[3],a4=wp[4],a5=wp[5],a6=wp[6],a7=wp[7],a8=wp[8];
            float p0c0=a0,                  p0c1=a1,                  p0c2=a2;
            float p1c0=0.5f*(a0+a3+a6),    p1c1=0.5f*(a1+a4+a7),     p1c2=0.5f*(a2+a5+a8);
            float p2c0=0.5f*(a0-a3+a6),    p2c1=0.5f*(a1-a4+a7),     p2c2=0.5f*(a2-a5+a8);
            float p3c0=a6,                  p3c1=a7,                  p3c2=a8;
            float U[16];
            U[ 0]=p0c0; U[ 1]=0.5f*(p0c0+p0c1+p0c2); U[ 2]=0.5f*(p0c0-p0c1+p0c2); U[ 3]=p0c2;
            U[ 4]=p1c0; U[ 5]=0.5f*(p1c0+p1c1+p1c2); U[ 6]=0.5f*(p1c0-p1c1+p1c2); U[ 7]=p1c2;
            U[ 8]=p2c0; U[ 9]=0.5f*(p2c0+p2c1+p2c2); U[10]=0.5f*(p2c0-p2c1+p2c2); U[11]=p2c2;
            U[12]=p3c0; U[13]=0.5f*(p3c0+p3c1+p3c2); U[14]=0.5f*(p3c0-p3c1+p3c2); U[15]=p3c2;
#pragma unroll
            for(int q=0;q<16;q++) sU[q*(CB*CG)+cl*CG+g]=U[q];
        }
        // ---- input transform V = Bt d B (ONE (cl,tile) unit per thread, float2 loads) ----
        {
            int cl=tid>>6, tile=tid&63;       // 4 cl x 64 tiles = 256 units
            int tr=(bx<<1)+(tile>>5), tc=tile&31;
            const float* ip = inb + (size_t)(cb0+cl)*IPLANE + (size_t)(tr*2)*66 + tc*2;
            float d[16];
#pragma unroll
            for(int r=0;r<4;r++){
                const float2* ip2=(const float2*)(ip + r*66);
                float2 va=__ldg(ip2), vb=__ldg(ip2+1);
                if constexpr (RIN){
                    va.x=fmaxf(va.x,0.f); va.y=fmaxf(va.y,0.f);
                    vb.x=fmaxf(vb.x,0.f); vb.y=fmaxf(vb.y,0.f);
                }
                d[r*4+0]=va.x; d[r*4+1]=va.y; d[r*4+2]=vb.x; d[r*4+3]=vb.y;
            }
            float w0[4],w1[4],w2[4],w3[4];
#pragma unroll
            for(int c=0;c<4;c++){
                w0[c]=d[c]-d[8+c];
                w1[c]=d[4+c]+d[8+c];
                w2[c]=d[8+c]-d[4+c];
                w3[c]=d[4+c]-d[12+c];
            }
            float V[16];
            V[ 0]=w0[0]-w0[2]; V[ 1]=w0[1]+w0[2]; V[ 2]=w0[2]-w0[1]; V[ 3]=w0[1]-w0[3];
            V[ 4]=w1[0]-w1[2]; V[ 5]=w1[1]+w1[2]; V[ 6]=w1[2]-w1[1]; V[ 7]=w1[1]-w1[3];
            V[ 8]=w2[0]-w2[2]; V[ 9]=w2[1]+w2[2]; V[10]=w2[2]-w2[1]; V[11]=w2[1]-w2[3];
            V[12]=w3[0]-w3[2]; V[13]=w3[1]+w3[2]; V[14]=w3[2]-w3[1]; V[15]=w3[1]-w3[3];
#pragma unroll
            for(int q=0;q<16;q++) sV[q*256 + tid] = V[q];
        }
        __syncthreads();
        // ---- transform-domain MMA (packed): 4cl x 4tiles x 8 pairs = 128 FFMA2/thread ----
#pragma unroll
        for(int cl=0;cl<CB;cl++){
            const ulonglong2* u2=(const ulonglong2*)(sU + p*(CB*CG) + cl*CG);
            u64 uv2[CG/2];
#pragma unroll
            for(int q=0;q<CG/4;q++){ ulonglong2 f=u2[q]; uv2[2*q]=f.x; uv2[2*q+1]=f.y; }
            float4 va=*(const float4*)(sV + p*256 + cl*64 + tg*4);
            u64 vv2[TJ]={bcast2(va.x),bcast2(va.y),bcast2(va.z),bcast2(va.w)};
#pragma unroll
            for(int j=0;j<TJ;j++)
#pragma unroll
                for(int q=0;q<CG/2;q++)
                    macc2[j][q]=ffma2(vv2[j],uv2[q],macc2[j][q]);
        }
    }

    // unpack accumulators for the epilogue
    float macc[TJ][CG];
#pragma unroll
    for(int j=0;j<TJ;j++)
#pragma unroll
        for(int q=0;q<CG/2;q++) unpack2(macc2[j][q], macc[j][2*q], macc[j][2*q+1]);

    // ---- epilogue: inverse transform Y = At M A, two 8-g halves through smem ----
    float* ob = out + (size_t)n*Cout*OPLANE + OOFF;
#pragma unroll
    for(int gh=0; gh<2; gh++){
        __syncthreads();
#pragma unroll
        for(int gs=0;gs<8;gs++)
#pragma unroll
            for(int j=0;j<TJ;j++){
                int unit = gs*64 + tg*TJ + j;     // 0..511
                sV[unit*17 + p] = macc[j][gh*8+gs];
            }
        __syncthreads();
#pragma unroll
        for(int k=0;k<2;k++){
            int unit = tid*2+k;                   // 0..511
            int gs = unit>>6, tile = unit&63;
            int tr=(bx<<1)+(tile>>5), tc=tile&31;
            float m[16];
#pragma unroll
            for(int q=0;q<16;q++) m[q]=sV[unit*17+q];
            float s0[4], s1[4];
#pragma unroll
            for(int c=0;c<4;c++){ s0[c]=m[c]+m[4+c]+m[8+c]; s1[c]=m[4+c]-m[8+c]-m[12+c]; }
            int co=co0+gh*8+gs;
            float b=bias[co];
            float y00=s0[0]+s0[1]+s0[2]+b;
            float y01=s0[1]-s0[2]-s0[3]+b;
            float y10=s1[0]+s1[1]+s1[2]+b;
            float y11=s1[1]-s1[2]-s1[3]+b;
            float* op = ob + (size_t)co*OPLANE + (size_t)(tr*2)*OPW + tc*2;
            op[0]=y00; op[1]=y01;
            op[OPW]=y10; op[OPW+1]=y11;
        }
    }
}

// ---------------- ConvTranspose2d k=4 s=2 p=1, gather, padded input ----------------
// Packed-FFMA2 when CG%4==0; scalar fallback otherwise (deconv2, CG=3).
template<int Cin,int Cout,int Hin,int Win,int CG,int PX,int IPW,int OPW,bool ROUT,bool TANH>
__global__ __launch_bounds__(256) void deconvp(
    const float* __restrict__ in, const float* __restrict__ w,
    const float* __restrict__ bias, float* __restrict__ out)
{
    constexpr int Hout=Hin*2, Wout=Win*2;
    constexpr int QHW=Hin*Win;
    constexpr int TILES=QHW/(256*PX);
    static_assert(QHW%(256*PX)==0 && 256%Win==0, "grid exactness");
    constexpr int IPLANE=IPW*(Hin+2);
    constexpr int IOFF=IPW+1;
    constexpr int OPADH=(OPW>Wout)?Hout+2:Hout;
    constexpr int OPLANE=OPW*OPADH;
    constexpr int OOFF=(OPW>Wout)?(OPW+1):0;
    constexpr int RJ=256/Win;
    constexpr bool PKD=(CG%4==0);
    constexpr int CGH=PKD?CG/2:1;
    constexpr int WSZ=Cin*4*CG;
    __shared__ __align__(16) float sw[WSZ];

    const int cls=blockIdx.x/TILES, tile=blockIdx.x%TILES;
    const int ph=cls>>1, pw=cls&1;
    const int co0=blockIdx.y*CG, n=blockIdx.z;

    for (int i=threadIdx.x;i<WSZ;i+=256){
        int g=i%CG, rest=i/CG;
        int ci=rest>>2, t=rest&3;
        int kh=(1-ph)+2*(t>>1), kw=(1-pw)+2*(t&1);
        sw[i]=w[(((size_t)ci*Cout+co0+g)*4+kh)*4+kw];
    }
    __syncthreads();

    const int base=tile*(256*PX)+threadIdx.x;
    const int qh0=base/Win, qw=base%Win;

    u64   acc2[PX][CGH];
    float accs[PX][PKD?1:CG];
    if constexpr (PKD){
#pragma unroll
        for(int q=0;q<CGH;q++){ u64 b=pack2(bias[co0+2*q], bias[co0+2*q+1]);
#pragma unroll
            for(int j=0;j<PX;j++) acc2[j][q]=b; }
    } else {
#pragma unroll
        for(int g=0;g<CG;g++){ float b=bias[co0+g];
#pragma unroll
            for(int j=0;j<PX;j++) accs[j][g]=b; }
    }

    const float* inb = in + (size_t)n*Cin*IPLANE + IOFF;
#pragma unroll 1
    for(int ci=0;ci<Cin;ci++){
        const float* ip = inb + (size_t)ci*IPLANE;
        float v[PX][4];
#pragma unroll
        for(int j=0;j<PX;j++){
            const int qh=qh0+j*RJ;
#pragma unroll
            for(int th=0;th<2;th++){
                const int ih=qh+ph-th;
#pragma unroll
                for(int tw=0;tw<2;tw++){
                    const int iw=qw+pw-tw;
                    v[j][th*2+tw]=__ldg(ip+ih*IPW+iw);
                }
            }
        }
#pragma unroll
        for(int t=0;t<4;t++){
            if constexpr (PKD){
                u64 wv[CGH];
                const ulonglong2* w4=(const ulonglong2*)(sw+(ci*4+t)*CG);
#pragma unroll
                for(int q=0;q<CG/4;q++){ ulonglong2 f=w4[q]; wv[2*q]=f.x; wv[2*q+1]=f.y; }
#pragma unroll
                for(int j=0;j<PX;j++){
                    u64 vb=bcast2(v[j][t]);
#pragma unroll
                    for(int q=0;q<CGH;q++) acc2[j][q]=ffma2(vb,wv[q],acc2[j][q]);
                }
            } else {
                float wv[CG];
#pragma unroll
                for(int g=0;g<CG;g++) wv[g]=sw[(ci*4+t)*CG+g];
#pragma unroll
                for(int j=0;j<PX;j++)
#pragma unroll
                    for(int g=0;g<CG;g++) accs[j][g]=fmaf(v[j][t],wv[g],accs[j][g]);
            }
        }
    }

    float* ob = out + (size_t)n*Cout*OPLANE + OOFF;
#pragma unroll
    for(int j=0;j<PX;j++){
        const int qh=qh0+j*RJ;
        const int oh=2*qh+ph, ow=2*qw+pw;
        if constexpr (PKD){
#pragma unroll
            for(int q=0;q<CGH;q++){
                float r0,r1; unpack2(acc2[j][q],r0,r1);
                if constexpr (ROUT){ r0=fmaxf(r0,0.f); r1=fmaxf(r1,0.f); }
                if constexpr (TANH){ r0=tanhf(r0); r1=tanhf(r1); }
                ob[(size_t)(co0+2*q  )*OPLANE + oh*OPW + ow]=r0;
                ob[(size_t)(co0+2*q+1)*OPLANE + oh*OPW + ow]=r1;
            }
        } else {
#pragma unroll
            for(int g=0;g<CG;g++){
                float r=accs[j][g];
                if constexpr (ROUT) r=fmaxf(r,0.f);
                if constexpr (TANH) r=tanhf(r);
                ob[(size_t)(co0+g)*OPLANE + oh*OPW + ow]=r;
            }
        }
    }
}

// ---------------- VQ (UNCHANGED — bit-exact reference rounding chain) ----------------
__global__ void zero_loss_k(){ g_loss_sum = 0.f; }

__global__ void cnorm_k(const float* __restrict__ cb){
    int c = blockIdx.x*blockDim.x + threadIdx.x;
    if (c < 512){
        float s = 0.f;
        const float* p = cb + (size_t)c*64;
#pragma unroll
        for (int d=0; d<64; d++) s = __fadd_rn(s, __fmul_rn(p[d], p[d]));
        g_cnorm[c] = s;
    }
}

__global__ __launch_bounds__(256) void vq_k(
    const float* __restrict__ z, const float* __restrict__ cb,
    float* __restrict__ quant)
{
    constexpr int D=64, NC=512, CHUNK=128;
    __shared__ __align__(16) float scode[CHUNK*D];
    __shared__ float snorm[CHUNK];
    __shared__ float sred[8];
    const int tid = threadIdx.x;
    const int p   = blockIdx.x*256 + tid;
    const int n   = p >> 12;
    const int hw  = p & 4095;
    const int h   = hw >> 6, wq = hw & 63;
    const float* zp = z + (size_t)n*D*4096 + hw;
    float zr[D];
#pragma unroll
    for (int d=0; d<D; d++) zr[d] = __ldg(zp + (size_t)d*4096);
    float zz = 0.f;
#pragma unroll
    for (int d=0; d<D; d++) zz = __fadd_rn(zz, __fmul_rn(zr[d], zr[d]));

    float best = 3.4e38f; int bidx = 0;
    for (int c0 = 0; c0 < NC; c0 += CHUNK){
        __syncthreads();
        for (int i = tid; i < CHUNK*D; i += 256) scode[i] = cb[(size_t)c0*D + i];
        if (tid < CHUNK) snorm[tid] = g_cnorm[c0 + tid];
        __syncthreads();
#pragma unroll 2
        for (int c = 0; c < CHUNK; c++){
            const float4* cp = (const float4*)(scode + c*D);
            float ip = 0.f;
#pragma unroll
            for (int q=0;q<16;q++){
                float4 e = cp[q];
                ip = fmaf(zr[4*q+0], e.x, ip);
                ip = fmaf(zr[4*q+1], e.y, ip);
                ip = fmaf(zr[4*q+2], e.z, ip);
                ip = fmaf(zr[4*q+3], e.w, ip);
            }
            float score = __fadd_rn(__fsub_rn(zz, __fmul_rn(2.f, ip)), snorm[c]);
            if (score < best){ best = score; bidx = c0 + c; }
        }
    }
    const float* cbp = cb + (size_t)bidx*D;
    float* qp = quant + (size_t)n*D*4356 + (h+1)*66 + (wq+1);
    float ssd = 0.f;
#pragma unroll
    for (int d=0; d<D; d++){
        float e  = __ldg(cbp + d);
        float df = e - zr[d];
        ssd = fmaf(df, df, ssd);
        qp[(size_t)d*4356] = e;
    }
#pragma unroll
    for (int o=16;o>0;o>>=1) ssd += __shfl_xor_sync(0xffffffffu, ssd, o);
    if ((tid & 31) == 0) sred[tid>>5] = ssd;
    __syncthreads();
    if (tid == 0){
        float s = 0.f;
#pragma unroll
        for (int i=0;i<8;i++) s += sred[i];
        atomicAdd(&g_loss_sum, s);
    }
}

__global__ void finalize_loss_k(float* __restrict__ out, int idx){
    out[idx] = 1.25f * g_loss_sum / 8388608.f;
}

// ---------------- host ----------------
extern "C" void kernel_launch(void* const* d_in, const int* in_sizes, int n_in,
                              void* d_out, int out_size)
{
    const float* x       = (const float*)d_in[0];
    const float* enc_w1  = (const float*)d_in[1];
    const float* enc_b1  = (const float*)d_in[2];
    const float* enc_w2  = (const float*)d_in[3];
    const float* enc_b2  = (const float*)d_in[4];
    const float* enc_w3  = (const float*)d_in[5];
    const float* enc_b3  = (const float*)d_in[6];
    const float* enc_rw1 = (const float*)d_in[7];
    const float* enc_rb1 = (const float*)d_in[8];
    const float* enc_rw2 = (const float*)d_in[9];
    const float* enc_rb2 = (const float*)d_in[10];
    const float* pvq_w   = (const float*)d_in[11];
    const float* pvq_b   = (const float*)d_in[12];
    const float* codebook= (const float*)d_in[13];
    const float* dec_w1  = (const float*)d_in[14];
    const float* dec_b1  = (const float*)d_in[15];
    const float* dec_rw1 = (const float*)d_in[16];
    const float* dec_rb1 = (const float*)d_in[17];
    const float* dec_rw2 = (const float*)d_in[18];
    const float* dec_rb2 = (const float*)d_in[19];
    const float* dt1_w   = (const float*)d_in[20];
    const float* dt1_b   = (const float*)d_in[21];
    const float* dt2_w   = (const float*)d_in[22];
    const float* dt2_b   = (const float*)d_in[23];
    float* out = (float*)d_out;

    float *A,*B,*C,*D,*E,*F;
    cudaGetSymbolAddress((void**)&A, g_bufA);
    cudaGetSymbolAddress((void**)&B, g_bufB);
    cudaGetSymbolAddress((void**)&C, g_bufC);
    cudaGetSymbolAddress((void**)&D, g_bufD);
    cudaGetSymbolAddress((void**)&E, g_bufE);
    cudaGetSymbolAddress((void**)&F, g_bufF);

    dim3 blk(256);

    // ---- halo re-zero ----
    zero_halo<2048,128,128><<<4128,256>>>(A);
    zero_halo<4096, 64, 64><<<4160,256>>>(B);
    zero_halo<4096, 64, 64><<<4160,256>>>(C);
    zero_halo<2048, 64, 64><<<2080,256>>>(F);

    // ---- Encoder ----
    // conv1: 3->64 k4 s2 p1 ReLU, x(256 unpadded, checked) -> A(pad130)
    convp<3,64,256,256,4,2,1, 8,4,3, 256,130, true ,false,true ,false><<<dim3(16,8,32),blk>>>(x, enc_w1, enc_b1, nullptr, A);
    // conv2: 64->128 k4 s2 p1 ReLU, A(pad130) -> B(pad66)
    convp<64,128,128,128,4,2,1, 16,4,32, 130,66, false,false,true ,false><<<dim3(4,8,32),blk>>>(A, enc_w2, enc_b2, nullptr, B);
    // conv3: 128->128 k3 s1 p1 (Winograd), B -> C
    winog<128,128,66,false><<<dim3(16,8,32),blk>>>(B, enc_w3, enc_b3, C);
    // enc res 0: 3x3 winograd (relu in) C->D(unpadded), 1x1(relu in) D->B (+C)
    winog<128,32,64,true><<<dim3(16,2,32),blk>>>(C, enc_rw1, enc_rb1, D);
    convp<32,128,64,64,1,1,0, 16,4,32, 64,66, false,true ,false,true ><<<dim3(4,8,32),blk>>>(D, enc_rw2, enc_rb2, C, B);
    // enc res 1 (+ final stack ReLU)
    winog<128,32,64,true><<<dim3(16,2,32),blk>>>(B, enc_rw1+32*128*9, enc_rb1+32, D);
    convp<32,128,64,64,1,1,0, 16,4,32, 64,66, false,true ,true ,true ><<<dim3(4,8,32),blk>>>(D, enc_rw2+128*32, enc_rb2+128, B, C);
    // pre-VQ 1x1: 128->64, C -> E(unpadded)
    convp<128,64,64,64,1,1,0, 16,4,128, 66,64, false,false,false,false><<<dim3(4,4,32),blk>>>(C, pvq_w, pvq_b, nullptr, E);

    // ---- VQ ----
    zero_loss_k<<<1,1>>>();
    cnorm_k<<<2,256>>>(codebook);
    vq_k<<<512,256>>>(E, codebook, F);

    // ---- Decoder ----
    // dec conv1: 64->128 k3 s1 p1 (Winograd), F(pad66) -> B
    winog<64,128,66,false><<<dim3(16,8,32),blk>>>(F, dec_w1, dec_b1, B);
    // dec res 0
    winog<128,32,64,true><<<dim3(16,2,32),blk>>>(B, dec_rw1, dec_rb1, D);
    convp<32,128,64,64,1,1,0, 16,4,32, 64,66, false,true ,false,true ><<<dim3(4,8,32),blk>>>(D, dec_rw2, dec_rb2, B, C);
    // dec res 1 (+ final ReLU)
    winog<128,32,64,true><<<dim3(16,2,32),blk>>>(C, dec_rw1+32*128*9, dec_rb1+32, D);
    convp<32,128,64,64,1,1,0, 16,4,32, 64,66, false,true ,true ,true ><<<dim3(4,8,32),blk>>>(D, dec_rw2+128*32, dec_rb2+128, C, B);
    // deconv1: 128->64, ReLU, B(pad66) -> A(pad130)
    deconvp<128,64,64,64, 16,4, 66,130, true ,false><<<dim3(16,4,32),blk>>>(B, dt1_w, dt1_b, A);
    // deconv2: 64->3, tanh, A(pad130) -> out(256 unpadded)
    deconvp<64,3,128,128, 3,8, 130,256, false,true ><<<dim3(32,1,32),blk>>>(A, dt2_w, dt2_b, out);

    // ---- loss scalar ----
    if (out_size > 32*3*256*256)
        finalize_loss_k<<<1,1>>>(out, out_size - 1);
}